// round 1
// baseline (speedup 1.0000x reference)
#include <cuda_runtime.h>
#include <math.h>

#define NN 50000
#define EE 640000
#define DD 128
#define EDIM 64
#define HH 4
#define ET (EE + NN)
#define LN_EPS 1e-5f

// ---------------------------------------------------------------------------
// Scratch (device globals: no allocation allowed)
// ---------------------------------------------------------------------------
__device__ __align__(16) float    g_xl[NN * DD];            // x @ Wl^T + bl
__device__ __align__(16) float    g_xr[NN * DD];            // x @ Wr^T + br
__device__ __align__(16) float    g_ep[(size_t)ET * DD];    // edge-attr projection (incl. self loops)
__device__ __align__(16) float    g_loop[NN * EDIM];        // mean incoming edge_attr per node
__device__              float     g_deg[NN];
__device__ __align__(16) unsigned g_amax[NN * HH];          // ordered-uint encoded float max
__device__ __align__(16) float    g_denom[NN * HH];
__device__ __align__(16) float    g_logits[(size_t)ET * HH];
__device__ __align__(16) float    g_ex[(size_t)ET * HH];
__device__ __align__(16) float    g_accum[NN * DD];         // GAT aggregation
__device__ __align__(16) float    g_h[NN * DD];             // LN1 output
__device__ __align__(16) float    g_mid[NN * 256];          // MLP hidden

// ---------------------------------------------------------------------------
// Helpers
// ---------------------------------------------------------------------------
__device__ __forceinline__ unsigned ford(float f) {
    unsigned u = __float_as_uint(f);
    return (u & 0x80000000u) ? ~u : (u | 0x80000000u);
}
__device__ __forceinline__ float iford(unsigned u) {
    return __uint_as_float((u & 0x80000000u) ? (u & 0x7FFFFFFFu) : ~u);
}
__device__ __forceinline__ void red_add_v4(float* p, float4 v) {
    asm volatile("red.global.add.v4.f32 [%0], {%1, %2, %3, %4};"
                 :: "l"(p), "f"(v.x), "f"(v.y), "f"(v.z), "f"(v.w) : "memory");
}
__device__ __forceinline__ float gelu_exact(float v) {
    return 0.5f * v * (1.0f + erff(v * 0.70710678118654752f));
}

// ---------------------------------------------------------------------------
// Init (re-zero accumulators every launch; graph is replayed)
// ---------------------------------------------------------------------------
__global__ void k_init() {
    int i = blockIdx.x * blockDim.x + threadIdx.x;
    if (i < NN * DD)   g_accum[i] = 0.0f;
    if (i < NN * EDIM) g_loop[i] = 0.0f;
    if (i < NN)        g_deg[i] = 0.0f;
    if (i < NN * HH) { g_amax[i] = 0u; g_denom[i] = 0.0f; }
}

// deg + loop_attr accumulation: 16 threads per edge (one float4 each)
__global__ void k_degloop(const int* __restrict__ ei, const float* __restrict__ ea) {
    int t = blockIdx.x * blockDim.x + threadIdx.x;
    if (t >= EE * 16) return;
    int e = t >> 4, q = t & 15;
    int dst = ei[EE + e];
    float4 v = *(const float4*)(ea + (size_t)e * EDIM + q * 4);
    red_add_v4(&g_loop[dst * EDIM + q * 4], v);
    if (q == 0) atomicAdd(&g_deg[dst], 1.0f);
}

__global__ void k_div() {
    int i = blockIdx.x * blockDim.x + threadIdx.x;
    if (i >= NN * EDIM) return;
    g_loop[i] /= fmaxf(g_deg[i >> 6], 1.0f);
}

// ---------------------------------------------------------------------------
// Generic SGEMM: C[M,Nc] = A[M,K] @ B[Nc,K]^T (+bias) (+gelu)
// 128x64 tile, BK=16, 256 threads, 8x4 per-thread microtile
// K % 16 == 0, Nc % 64 == 0 required; M guarded.
// ---------------------------------------------------------------------------
__global__ __launch_bounds__(256) void k_sgemm(
    const float* __restrict__ A, const float* __restrict__ B,
    const float* __restrict__ bias, float* __restrict__ C,
    int M, int K, int Nc, int act)
{
    __shared__ __align__(16) float As[16][128];
    __shared__ __align__(16) float Bs[16][64];
    int tid = threadIdx.x;
    int m0 = blockIdx.y * 128, n0 = blockIdx.x * 64;
    int tx = tid & 15, ty = tid >> 4;
    float acc[8][4];
#pragma unroll
    for (int i = 0; i < 8; i++)
#pragma unroll
        for (int j = 0; j < 4; j++) acc[i][j] = 0.0f;

    int la_m = tid >> 1, la_k = (tid & 1) * 8;
    int lb_n = tid >> 2, lb_k = (tid & 3) * 4;

    for (int k0 = 0; k0 < K; k0 += 16) {
        int arow = m0 + la_m;
        float4 v0 = make_float4(0.f, 0.f, 0.f, 0.f), v1 = v0;
        if (arow < M) {
            const float* ap = A + (size_t)arow * K + k0 + la_k;
            v0 = *(const float4*)ap;
            v1 = *(const float4*)(ap + 4);
        }
        As[la_k + 0][la_m] = v0.x; As[la_k + 1][la_m] = v0.y;
        As[la_k + 2][la_m] = v0.z; As[la_k + 3][la_m] = v0.w;
        As[la_k + 4][la_m] = v1.x; As[la_k + 5][la_m] = v1.y;
        As[la_k + 6][la_m] = v1.z; As[la_k + 7][la_m] = v1.w;

        const float* bp = B + (size_t)(n0 + lb_n) * K + k0 + lb_k;
        float4 bv = *(const float4*)bp;
        Bs[lb_k + 0][lb_n] = bv.x; Bs[lb_k + 1][lb_n] = bv.y;
        Bs[lb_k + 2][lb_n] = bv.z; Bs[lb_k + 3][lb_n] = bv.w;
        __syncthreads();

#pragma unroll
        for (int k = 0; k < 16; k++) {
            float4 b4 = *(float4*)&Bs[k][tx * 4];
            float4 a0 = *(float4*)&As[k][ty * 8];
            float4 a1 = *(float4*)&As[k][ty * 8 + 4];
            float a[8] = {a0.x, a0.y, a0.z, a0.w, a1.x, a1.y, a1.z, a1.w};
            float b[4] = {b4.x, b4.y, b4.z, b4.w};
#pragma unroll
            for (int i = 0; i < 8; i++)
#pragma unroll
                for (int j = 0; j < 4; j++)
                    acc[i][j] += a[i] * b[j];
        }
        __syncthreads();
    }

#pragma unroll
    for (int i = 0; i < 8; i++) {
        int row = m0 + ty * 8 + i;
        if (row >= M) continue;
        int col = n0 + tx * 4;
        float4 r = make_float4(acc[i][0], acc[i][1], acc[i][2], acc[i][3]);
        if (bias) {
            r.x += bias[col]; r.y += bias[col + 1];
            r.z += bias[col + 2]; r.w += bias[col + 3];
        }
        if (act == 1) {
            r.x = gelu_exact(r.x); r.y = gelu_exact(r.y);
            r.z = gelu_exact(r.z); r.w = gelu_exact(r.w);
        }
        *(float4*)(C + (size_t)row * Nc + col) = r;
    }
}

// ---------------------------------------------------------------------------
// Edge logits + segment max (warp per edge)
// ---------------------------------------------------------------------------
__global__ void k_logits(const int* __restrict__ ei, const float* __restrict__ att) {
    int w = (blockIdx.x * blockDim.x + threadIdx.x) >> 5;
    if (w >= ET) return;
    int lane = threadIdx.x & 31;
    int src = (w < EE) ? ei[w] : (w - EE);
    int dst = (w < EE) ? ei[EE + w] : (w - EE);
    const float* ep = g_ep + (size_t)w * DD;
    const float* xl = g_xl + (size_t)src * DD;
    const float* xr = g_xr + (size_t)dst * DD;

    float p0, p1, p2, p3;
    {
        int i0 = lane, i1 = 32 + lane, i2 = 64 + lane, i3 = 96 + lane;
        float v0 = xl[i0] + xr[i0] + __ldcs(ep + i0);
        float v1 = xl[i1] + xr[i1] + __ldcs(ep + i1);
        float v2 = xl[i2] + xr[i2] + __ldcs(ep + i2);
        float v3 = xl[i3] + xr[i3] + __ldcs(ep + i3);
        v0 = (v0 > 0.f) ? v0 : 0.2f * v0;
        v1 = (v1 > 0.f) ? v1 : 0.2f * v1;
        v2 = (v2 > 0.f) ? v2 : 0.2f * v2;
        v3 = (v3 > 0.f) ? v3 : 0.2f * v3;
        p0 = v0 * att[i0]; p1 = v1 * att[i1];
        p2 = v2 * att[i2]; p3 = v3 * att[i3];
    }
#pragma unroll
    for (int off = 16; off; off >>= 1) {
        p0 += __shfl_xor_sync(0xFFFFFFFFu, p0, off);
        p1 += __shfl_xor_sync(0xFFFFFFFFu, p1, off);
        p2 += __shfl_xor_sync(0xFFFFFFFFu, p2, off);
        p3 += __shfl_xor_sync(0xFFFFFFFFu, p3, off);
    }
    if (lane < 4) {
        float lv = (lane == 0) ? p0 : (lane == 1) ? p1 : (lane == 2) ? p2 : p3;
        g_logits[(size_t)w * 4 + lane] = lv;
        atomicMax(&g_amax[dst * 4 + lane], ford(lv));
    }
}

// exp + segment sum (thread per edge)
__global__ void k_exps(const int* __restrict__ ei) {
    int t = blockIdx.x * blockDim.x + threadIdx.x;
    if (t >= ET) return;
    int dst = (t < EE) ? ei[EE + t] : (t - EE);
    float4 lg = *(float4*)&g_logits[(size_t)t * 4];
    uint4 am = *(uint4*)&g_amax[dst * 4];
    float4 e;
    e.x = expf(lg.x - iford(am.x));
    e.y = expf(lg.y - iford(am.y));
    e.z = expf(lg.z - iford(am.z));
    e.w = expf(lg.w - iford(am.w));
    *(float4*)&g_ex[(size_t)t * 4] = e;
    red_add_v4(&g_denom[dst * 4], e);
}

// alpha + weighted aggregation (warp per edge, one v4-red per lane)
__global__ void k_agg(const int* __restrict__ ei, float* __restrict__ outAlpha) {
    int w = (blockIdx.x * blockDim.x + threadIdx.x) >> 5;
    if (w >= ET) return;
    int lane = threadIdx.x & 31;
    int src = (w < EE) ? ei[w] : (w - EE);
    int dst = (w < EE) ? ei[EE + w] : (w - EE);
    int h = lane >> 3;
    float a = g_ex[(size_t)w * 4 + h] / g_denom[dst * 4 + h];
    float4 x = *(const float4*)&g_xl[(size_t)src * DD + lane * 4];
    red_add_v4(&g_accum[dst * DD + lane * 4],
               make_float4(x.x * a, x.y * a, x.z * a, x.w * a));
    if (outAlpha != nullptr && lane < 4)
        outAlpha[(size_t)w * 4 + lane] =
            g_ex[(size_t)w * 4 + lane] / g_denom[dst * 4 + lane];
}

__global__ void k_ei(const int* __restrict__ ei, float* __restrict__ outEI) {
    int t = blockIdx.x * blockDim.x + threadIdx.x;
    if (t >= ET) return;
    int s = (t < EE) ? ei[t] : (t - EE);
    int d = (t < EE) ? ei[EE + t] : (t - EE);
    outEI[t] = (float)s;
    outEI[ET + t] = (float)d;
}

// LN1: h = LayerNorm(x + gat_out + gat_bias) (warp per node)
__global__ void k_ln1(const float* __restrict__ x, const float* __restrict__ gb,
                      const float* __restrict__ gam, const float* __restrict__ bet) {
    int w = (blockIdx.x * blockDim.x + threadIdx.x) >> 5;
    if (w >= NN) return;
    int lane = threadIdx.x & 31;
    float v[4];
#pragma unroll
    for (int r = 0; r < 4; r++) {
        int idx = r * 32 + lane;
        v[r] = x[(size_t)w * DD + idx] + g_accum[(size_t)w * DD + idx] + gb[idx];
    }
    float s = v[0] + v[1] + v[2] + v[3];
#pragma unroll
    for (int off = 16; off; off >>= 1) s += __shfl_xor_sync(0xFFFFFFFFu, s, off);
    float mu = s * (1.0f / 128.0f);
    float q = 0.f;
#pragma unroll
    for (int r = 0; r < 4; r++) { float d = v[r] - mu; q += d * d; }
#pragma unroll
    for (int off = 16; off; off >>= 1) q += __shfl_xor_sync(0xFFFFFFFFu, q, off);
    float rstd = rsqrtf(q * (1.0f / 128.0f) + LN_EPS);
#pragma unroll
    for (int r = 0; r < 4; r++) {
        int idx = r * 32 + lane;
        g_h[(size_t)w * DD + idx] = (v[r] - mu) * rstd * gam[idx] + bet[idx];
    }
}

// LN2: out = LayerNorm(h + mlp) -> d_out (mlp result lives in g_xl, reused)
__global__ void k_ln2(const float* __restrict__ gam, const float* __restrict__ bet,
                      float* __restrict__ out) {
    int w = (blockIdx.x * blockDim.x + threadIdx.x) >> 5;
    if (w >= NN) return;
    int lane = threadIdx.x & 31;
    float v[4];
#pragma unroll
    for (int r = 0; r < 4; r++) {
        int idx = r * 32 + lane;
        v[r] = g_h[(size_t)w * DD + idx] + g_xl[(size_t)w * DD + idx];
    }
    float s = v[0] + v[1] + v[2] + v[3];
#pragma unroll
    for (int off = 16; off; off >>= 1) s += __shfl_xor_sync(0xFFFFFFFFu, s, off);
    float mu = s * (1.0f / 128.0f);
    float q = 0.f;
#pragma unroll
    for (int r = 0; r < 4; r++) { float d = v[r] - mu; q += d * d; }
#pragma unroll
    for (int off = 16; off; off >>= 1) q += __shfl_xor_sync(0xFFFFFFFFu, q, off);
    float rstd = rsqrtf(q * (1.0f / 128.0f) + LN_EPS);
#pragma unroll
    for (int r = 0; r < 4; r++) {
        int idx = r * 32 + lane;
        out[(size_t)w * DD + idx] = (v[r] - mu) * rstd * gam[idx] + bet[idx];
    }
}

// ---------------------------------------------------------------------------
// Launch
// ---------------------------------------------------------------------------
extern "C" void kernel_launch(void* const* d_in, const int* in_sizes, int n_in,
                              void* d_out, int out_size) {
    const float* x    = (const float*)d_in[0];
    const int*   ei   = (const int*)d_in[1];
    const float* ea   = (const float*)d_in[2];
    const float* Wl   = (const float*)d_in[3];
    const float* bl   = (const float*)d_in[4];
    const float* Wr   = (const float*)d_in[5];
    const float* br   = (const float*)d_in[6];
    const float* We   = (const float*)d_in[7];
    const float* att  = (const float*)d_in[8];
    const float* gb   = (const float*)d_in[9];
    const float* l1g  = (const float*)d_in[10];
    const float* l1b  = (const float*)d_in[11];
    const float* l2g  = (const float*)d_in[12];
    const float* l2b  = (const float*)d_in[13];
    const float* W1   = (const float*)d_in[14];
    const float* W2   = (const float*)d_in[15];
    float* out = (float*)d_out;

    long long full = (long long)NN * DD + 2LL * ET + (long long)ET * HH;
    bool fullout = ((long long)out_size == full);
    float* outEI    = fullout ? out + (size_t)NN * DD : nullptr;
    float* outAlpha = fullout ? out + (size_t)NN * DD + 2 * (size_t)ET : nullptr;

    float *pxl, *pxr, *pep, *ploop, *ph, *pmid;
    cudaGetSymbolAddress((void**)&pxl, g_xl);
    cudaGetSymbolAddress((void**)&pxr, g_xr);
    cudaGetSymbolAddress((void**)&pep, g_ep);
    cudaGetSymbolAddress((void**)&ploop, g_loop);
    cudaGetSymbolAddress((void**)&ph, g_h);
    cudaGetSymbolAddress((void**)&pmid, g_mid);

    const int T = 256;
    k_init<<<(NN * DD + T - 1) / T, T>>>();
    k_degloop<<<(EE * 16 + T - 1) / T, T>>>(ei, ea);
    k_div<<<(NN * EDIM + T - 1) / T, T>>>();

    dim3 gxl(DD / 64, (NN + 127) / 128);
    k_sgemm<<<gxl, 256>>>(x, Wl, bl, pxl, NN, DD, DD, 0);
    k_sgemm<<<gxl, 256>>>(x, Wr, br, pxr, NN, DD, DD, 0);

    dim3 ge1(DD / 64, (EE + 127) / 128);
    k_sgemm<<<ge1, 256>>>(ea, We, nullptr, pep, EE, EDIM, DD, 0);
    dim3 ge2(DD / 64, (NN + 127) / 128);
    k_sgemm<<<ge2, 256>>>(ploop, We, nullptr, pep + (size_t)EE * DD, NN, EDIM, DD, 0);

    k_logits<<<(ET * 32 + T - 1) / T, T>>>(ei, att);
    k_exps<<<(ET + T - 1) / T, T>>>(ei);
    k_agg<<<(ET * 32 + T - 1) / T, T>>>(ei, outAlpha);
    if (fullout) k_ei<<<(ET + T - 1) / T, T>>>(ei, outEI);

    k_ln1<<<(NN * 32 + T - 1) / T, T>>>(x, gb, l1g, l1b);

    dim3 gm1(256 / 64, (NN + 127) / 128);
    k_sgemm<<<gm1, 256>>>(ph, W1, nullptr, pmid, NN, DD, 256, 1);
    dim3 gm2(DD / 64, (NN + 127) / 128);
    k_sgemm<<<gm2, 256>>>(pmid, W2, nullptr, pxl, NN, 256, DD, 0);

    k_ln2<<<(NN * 32 + T - 1) / T, T>>>(l2g, l2b, out);
}

// round 2
// speedup vs baseline: 1.0308x; 1.0308x over previous
#include <cuda_runtime.h>
#include <math.h>

#define NN 50000
#define EE 640000
#define DD 128
#define EDIM 64
#define HH 4
#define ET (EE + NN)
#define LN_EPS 1e-5f

// ---------------------------------------------------------------------------
// Scratch (device globals: no allocation allowed)
// ---------------------------------------------------------------------------
__device__ __align__(16) float    g_xlr[(size_t)NN * 256];  // [xl | xr] fused projection
__device__ __align__(16) float    g_wlr[256 * DD];          // packed [Wl; Wr]
__device__ __align__(16) float    g_blr[256];               // packed [bl; br]
__device__ __align__(16) float    g_ep[(size_t)ET * DD];    // edge projection (also reused for MLP2 out)
__device__ __align__(16) float    g_loop[NN * EDIM];
__device__              float     g_deg[NN];
__device__ __align__(16) unsigned g_amax[NN * HH];
__device__ __align__(16) float    g_denom[NN * HH];
__device__ __align__(16) float    g_logits[(size_t)ET * HH];
__device__ __align__(16) float    g_ex[(size_t)ET * HH];
__device__ __align__(16) float    g_accum[NN * DD];
__device__ __align__(16) float    g_h[NN * DD];
__device__ __align__(16) float    g_mid[(size_t)NN * 256];

// ---------------------------------------------------------------------------
// Helpers
// ---------------------------------------------------------------------------
__device__ __forceinline__ unsigned ford(float f) {
    unsigned u = __float_as_uint(f);
    return (u & 0x80000000u) ? ~u : (u | 0x80000000u);
}
__device__ __forceinline__ float iford(unsigned u) {
    return __uint_as_float((u & 0x80000000u) ? (u & 0x7FFFFFFFu) : ~u);
}
__device__ __forceinline__ void red_add_v4(float* p, float4 v) {
    asm volatile("red.global.add.v4.f32 [%0], {%1, %2, %3, %4};"
                 :: "l"(p), "f"(v.x), "f"(v.y), "f"(v.z), "f"(v.w) : "memory");
}
__device__ __forceinline__ float gelu_exact(float v) {
    return 0.5f * v * (1.0f + erff(v * 0.70710678118654752f));
}

// ---------------------------------------------------------------------------
// Init
// ---------------------------------------------------------------------------
__global__ void k_init() {
    int i = blockIdx.x * blockDim.x + threadIdx.x;
    if (i < NN * DD)   g_accum[i] = 0.0f;
    if (i < NN * EDIM) g_loop[i] = 0.0f;
    if (i < NN)        g_deg[i] = 0.0f;
    if (i < NN * HH) { g_amax[i] = 0u; g_denom[i] = 0.0f; }
}

__global__ void k_pack(const float* __restrict__ Wl, const float* __restrict__ Wr,
                       const float* __restrict__ bl, const float* __restrict__ br) {
    int i = blockIdx.x * blockDim.x + threadIdx.x;
    if (i < 128 * DD) {
        g_wlr[i] = Wl[i];
        g_wlr[128 * DD + i] = Wr[i];
    }
    if (i < 128) { g_blr[i] = bl[i]; g_blr[128 + i] = br[i]; }
}

__global__ void k_degloop(const int* __restrict__ ei, const float* __restrict__ ea) {
    int t = blockIdx.x * blockDim.x + threadIdx.x;
    if (t >= EE * 16) return;
    int e = t >> 4, q = t & 15;
    int dst = ei[EE + e];
    float4 v = *(const float4*)(ea + (size_t)e * EDIM + q * 4);
    red_add_v4(&g_loop[dst * EDIM + q * 4], v);
    if (q == 0) atomicAdd(&g_deg[dst], 1.0f);
}

__global__ void k_div() {
    int i = blockIdx.x * blockDim.x + threadIdx.x;
    if (i >= NN * EDIM) return;
    g_loop[i] /= fmaxf(g_deg[i >> 6], 1.0f);
}

// ---------------------------------------------------------------------------
// SGEMM: C[M,Nc] = A[M,K] @ B[Nc,K]^T (+bias) (+gelu)
// 128x128 tile, BK=8, 256 threads, 8x8 microtile (split-by-64 mapping),
// double-buffered smem with register prefetch.
// Requires K % 8 == 0, Nc % 128 == 0. M guarded.
// ---------------------------------------------------------------------------
__global__ __launch_bounds__(256, 2) void k_sgemm(
    const float* __restrict__ A, const float* __restrict__ B,
    const float* __restrict__ bias, float* __restrict__ C,
    int M, int K, int Nc, int act)
{
    __shared__ __align__(16) float As[2][8][132];
    __shared__ __align__(16) float Bs[2][8][132];
    int tid = threadIdx.x;
    int m0 = blockIdx.y * 128, n0 = blockIdx.x * 128;
    int tx = tid & 15, ty = tid >> 4;      // 16x16 thread grid

    int lr = tid >> 1;                     // 0..127 (tile row for loads)
    int lk = (tid & 1) * 4;                // k 0 or 4

    const float* aptr = A + (size_t)(m0 + lr) * K + lk;
    const float* bptr = B + (size_t)(n0 + lr) * K + lk;
    bool aval = (m0 + lr) < M;

    float4 av = aval ? *(const float4*)aptr : make_float4(0.f,0.f,0.f,0.f);
    float4 bv = *(const float4*)bptr;

    float acc[8][8];
#pragma unroll
    for (int i = 0; i < 8; i++)
#pragma unroll
        for (int j = 0; j < 8; j++) acc[i][j] = 0.0f;

    int nk = K >> 3;
    int buf = 0;

    As[0][lk+0][lr] = av.x; As[0][lk+1][lr] = av.y;
    As[0][lk+2][lr] = av.z; As[0][lk+3][lr] = av.w;
    Bs[0][lk+0][lr] = bv.x; Bs[0][lk+1][lr] = bv.y;
    Bs[0][lk+2][lr] = bv.z; Bs[0][lk+3][lr] = bv.w;
    __syncthreads();

    for (int it = 0; it < nk; it++) {
        if (it + 1 < nk) {
            av = aval ? *(const float4*)(aptr + (it + 1) * 8) : make_float4(0.f,0.f,0.f,0.f);
            bv = *(const float4*)(bptr + (it + 1) * 8);
        }
#pragma unroll
        for (int k = 0; k < 8; k++) {
            float4 a0 = *(float4*)&As[buf][k][ty * 4];
            float4 a1 = *(float4*)&As[buf][k][64 + ty * 4];
            float4 b0 = *(float4*)&Bs[buf][k][tx * 4];
            float4 b1 = *(float4*)&Bs[buf][k][64 + tx * 4];
            float a[8] = {a0.x, a0.y, a0.z, a0.w, a1.x, a1.y, a1.z, a1.w};
            float b[8] = {b0.x, b0.y, b0.z, b0.w, b1.x, b1.y, b1.z, b1.w};
#pragma unroll
            for (int i = 0; i < 8; i++)
#pragma unroll
                for (int j = 0; j < 8; j++)
                    acc[i][j] += a[i] * b[j];
        }
        if (it + 1 < nk) {
            int nb = buf ^ 1;
            As[nb][lk+0][lr] = av.x; As[nb][lk+1][lr] = av.y;
            As[nb][lk+2][lr] = av.z; As[nb][lk+3][lr] = av.w;
            Bs[nb][lk+0][lr] = bv.x; Bs[nb][lk+1][lr] = bv.y;
            Bs[nb][lk+2][lr] = bv.z; Bs[nb][lk+3][lr] = bv.w;
            __syncthreads();
            buf = nb;
        }
    }

    // Epilogue: rows {ty*4+i, 64+ty*4+i}, cols {tx*4+j, 64+tx*4+j}
#pragma unroll
    for (int ih = 0; ih < 2; ih++) {
#pragma unroll
        for (int i = 0; i < 4; i++) {
            int row = m0 + ih * 64 + ty * 4 + i;
            if (row >= M) continue;
            int ai = ih * 4 + i;
#pragma unroll
            for (int jh = 0; jh < 2; jh++) {
                int col = n0 + jh * 64 + tx * 4;
                float4 r = make_float4(acc[ai][jh*4+0], acc[ai][jh*4+1],
                                       acc[ai][jh*4+2], acc[ai][jh*4+3]);
                if (bias) {
                    float4 bb = *(const float4*)(bias + col);
                    r.x += bb.x; r.y += bb.y; r.z += bb.z; r.w += bb.w;
                }
                if (act == 1) {
                    r.x = gelu_exact(r.x); r.y = gelu_exact(r.y);
                    r.z = gelu_exact(r.z); r.w = gelu_exact(r.w);
                }
                *(float4*)(C + (size_t)row * Nc + col) = r;
            }
        }
    }
}

// ---------------------------------------------------------------------------
// Edge logits + segment max (warp per edge). xl = g_xlr[.,0:128], xr = [.,128:256]
// ---------------------------------------------------------------------------
__global__ void k_logits(const int* __restrict__ ei, const float* __restrict__ att) {
    int w = (blockIdx.x * blockDim.x + threadIdx.x) >> 5;
    if (w >= ET) return;
    int lane = threadIdx.x & 31;
    int src = (w < EE) ? ei[w] : (w - EE);
    int dst = (w < EE) ? ei[EE + w] : (w - EE);
    const float* ep = g_ep + (size_t)w * DD;
    const float* xl = g_xlr + (size_t)src * 256;
    const float* xr = g_xlr + (size_t)dst * 256 + 128;

    float p0, p1, p2, p3;
    {
        int i0 = lane, i1 = 32 + lane, i2 = 64 + lane, i3 = 96 + lane;
        float v0 = xl[i0] + xr[i0] + __ldcs(ep + i0);
        float v1 = xl[i1] + xr[i1] + __ldcs(ep + i1);
        float v2 = xl[i2] + xr[i2] + __ldcs(ep + i2);
        float v3 = xl[i3] + xr[i3] + __ldcs(ep + i3);
        v0 = (v0 > 0.f) ? v0 : 0.2f * v0;
        v1 = (v1 > 0.f) ? v1 : 0.2f * v1;
        v2 = (v2 > 0.f) ? v2 : 0.2f * v2;
        v3 = (v3 > 0.f) ? v3 : 0.2f * v3;
        p0 = v0 * att[i0]; p1 = v1 * att[i1];
        p2 = v2 * att[i2]; p3 = v3 * att[i3];
    }
#pragma unroll
    for (int off = 16; off; off >>= 1) {
        p0 += __shfl_xor_sync(0xFFFFFFFFu, p0, off);
        p1 += __shfl_xor_sync(0xFFFFFFFFu, p1, off);
        p2 += __shfl_xor_sync(0xFFFFFFFFu, p2, off);
        p3 += __shfl_xor_sync(0xFFFFFFFFu, p3, off);
    }
    if (lane < 4) {
        float lv = (lane == 0) ? p0 : (lane == 1) ? p1 : (lane == 2) ? p2 : p3;
        g_logits[(size_t)w * 4 + lane] = lv;
        atomicMax(&g_amax[dst * 4 + lane], ford(lv));
    }
}

__global__ void k_exps(const int* __restrict__ ei) {
    int t = blockIdx.x * blockDim.x + threadIdx.x;
    if (t >= ET) return;
    int dst = (t < EE) ? ei[EE + t] : (t - EE);
    float4 lg = *(float4*)&g_logits[(size_t)t * 4];
    uint4 am = *(uint4*)&g_amax[dst * 4];
    float4 e;
    e.x = expf(lg.x - iford(am.x));
    e.y = expf(lg.y - iford(am.y));
    e.z = expf(lg.z - iford(am.z));
    e.w = expf(lg.w - iford(am.w));
    *(float4*)&g_ex[(size_t)t * 4] = e;
    red_add_v4(&g_denom[dst * 4], e);
}

__global__ void k_agg(const int* __restrict__ ei, float* __restrict__ outAlpha) {
    int w = (blockIdx.x * blockDim.x + threadIdx.x) >> 5;
    if (w >= ET) return;
    int lane = threadIdx.x & 31;
    int src = (w < EE) ? ei[w] : (w - EE);
    int dst = (w < EE) ? ei[EE + w] : (w - EE);
    int h = lane >> 3;
    float a = g_ex[(size_t)w * 4 + h] / g_denom[dst * 4 + h];
    float4 x = *(const float4*)&g_xlr[(size_t)src * 256 + lane * 4];
    red_add_v4(&g_accum[dst * DD + lane * 4],
               make_float4(x.x * a, x.y * a, x.z * a, x.w * a));
    if (outAlpha != nullptr && lane < 4)
        outAlpha[(size_t)w * 4 + lane] =
            g_ex[(size_t)w * 4 + lane] / g_denom[dst * 4 + lane];
}

__global__ void k_ei(const int* __restrict__ ei, float* __restrict__ outEI) {
    int t = blockIdx.x * blockDim.x + threadIdx.x;
    if (t >= ET) return;
    int s = (t < EE) ? ei[t] : (t - EE);
    int d = (t < EE) ? ei[EE + t] : (t - EE);
    outEI[t] = (float)s;
    outEI[ET + t] = (float)d;
}

__global__ void k_ln1(const float* __restrict__ x, const float* __restrict__ gb,
                      const float* __restrict__ gam, const float* __restrict__ bet) {
    int w = (blockIdx.x * blockDim.x + threadIdx.x) >> 5;
    if (w >= NN) return;
    int lane = threadIdx.x & 31;
    float v[4];
#pragma unroll
    for (int r = 0; r < 4; r++) {
        int idx = r * 32 + lane;
        v[r] = x[(size_t)w * DD + idx] + g_accum[(size_t)w * DD + idx] + gb[idx];
    }
    float s = v[0] + v[1] + v[2] + v[3];
#pragma unroll
    for (int off = 16; off; off >>= 1) s += __shfl_xor_sync(0xFFFFFFFFu, s, off);
    float mu = s * (1.0f / 128.0f);
    float q = 0.f;
#pragma unroll
    for (int r = 0; r < 4; r++) { float d = v[r] - mu; q += d * d; }
#pragma unroll
    for (int off = 16; off; off >>= 1) q += __shfl_xor_sync(0xFFFFFFFFu, q, off);
    float rstd = rsqrtf(q * (1.0f / 128.0f) + LN_EPS);
#pragma unroll
    for (int r = 0; r < 4; r++) {
        int idx = r * 32 + lane;
        g_h[(size_t)w * DD + idx] = (v[r] - mu) * rstd * gam[idx] + bet[idx];
    }
}

// LN2: out = LayerNorm(h + mlp2) ; mlp2 result lives in g_ep (reused)
__global__ void k_ln2(const float* __restrict__ gam, const float* __restrict__ bet,
                      float* __restrict__ out) {
    int w = (blockIdx.x * blockDim.x + threadIdx.x) >> 5;
    if (w >= NN) return;
    int lane = threadIdx.x & 31;
    float v[4];
#pragma unroll
    for (int r = 0; r < 4; r++) {
        int idx = r * 32 + lane;
        v[r] = g_h[(size_t)w * DD + idx] + g_ep[(size_t)w * DD + idx];
    }
    float s = v[0] + v[1] + v[2] + v[3];
#pragma unroll
    for (int off = 16; off; off >>= 1) s += __shfl_xor_sync(0xFFFFFFFFu, s, off);
    float mu = s * (1.0f / 128.0f);
    float q = 0.f;
#pragma unroll
    for (int r = 0; r < 4; r++) { float d = v[r] - mu; q += d * d; }
#pragma unroll
    for (int off = 16; off; off >>= 1) q += __shfl_xor_sync(0xFFFFFFFFu, q, off);
    float rstd = rsqrtf(q * (1.0f / 128.0f) + LN_EPS);
#pragma unroll
    for (int r = 0; r < 4; r++) {
        int idx = r * 32 + lane;
        out[(size_t)w * DD + idx] = (v[r] - mu) * rstd * gam[idx] + bet[idx];
    }
}

// ---------------------------------------------------------------------------
// Launch
// ---------------------------------------------------------------------------
extern "C" void kernel_launch(void* const* d_in, const int* in_sizes, int n_in,
                              void* d_out, int out_size) {
    const float* x    = (const float*)d_in[0];
    const int*   ei   = (const int*)d_in[1];
    const float* ea   = (const float*)d_in[2];
    const float* Wl   = (const float*)d_in[3];
    const float* bl   = (const float*)d_in[4];
    const float* Wr   = (const float*)d_in[5];
    const float* br   = (const float*)d_in[6];
    const float* We   = (const float*)d_in[7];
    const float* att  = (const float*)d_in[8];
    const float* gb   = (const float*)d_in[9];
    const float* l1g  = (const float*)d_in[10];
    const float* l1b  = (const float*)d_in[11];
    const float* l2g  = (const float*)d_in[12];
    const float* l2b  = (const float*)d_in[13];
    const float* W1   = (const float*)d_in[14];
    const float* W2   = (const float*)d_in[15];
    float* out = (float*)d_out;

    long long full = (long long)NN * DD + 2LL * ET + (long long)ET * HH;
    bool fullout = ((long long)out_size == full);
    float* outEI    = fullout ? out + (size_t)NN * DD : nullptr;
    float* outAlpha = fullout ? out + (size_t)NN * DD + 2 * (size_t)ET : nullptr;

    float *pxlr, *pwlr, *pblr, *pep, *ploop, *ph, *pmid;
    cudaGetSymbolAddress((void**)&pxlr, g_xlr);
    cudaGetSymbolAddress((void**)&pwlr, g_wlr);
    cudaGetSymbolAddress((void**)&pblr, g_blr);
    cudaGetSymbolAddress((void**)&pep, g_ep);
    cudaGetSymbolAddress((void**)&ploop, g_loop);
    cudaGetSymbolAddress((void**)&ph, g_h);
    cudaGetSymbolAddress((void**)&pmid, g_mid);

    const int T = 256;
    k_init<<<(NN * DD + T - 1) / T, T>>>();
    k_pack<<<(128 * DD + T - 1) / T, T>>>(Wl, Wr, bl, br);
    k_degloop<<<(EE * 16 + T - 1) / T, T>>>(ei, ea);
    k_div<<<(NN * EDIM + T - 1) / T, T>>>();

    // fused xl|xr projection: [N,128] @ [256,128]^T -> [N,256]
    dim3 gxlr(2, (NN + 127) / 128);
    k_sgemm<<<gxlr, 256>>>(x, pwlr, pblr, pxlr, NN, DD, 256, 0);

    // edge projections
    dim3 ge1(1, (EE + 127) / 128);
    k_sgemm<<<ge1, 256>>>(ea, We, nullptr, pep, EE, EDIM, DD, 0);
    dim3 ge2(1, (NN + 127) / 128);
    k_sgemm<<<ge2, 256>>>(ploop, We, nullptr, pep + (size_t)EE * DD, NN, EDIM, DD, 0);

    k_logits<<<(ET * 32 + T - 1) / T, T>>>(ei, att);
    k_exps<<<(ET + T - 1) / T, T>>>(ei);
    k_agg<<<(ET * 32 + T - 1) / T, T>>>(ei, outAlpha);
    if (fullout) k_ei<<<(ET + T - 1) / T, T>>>(ei, outEI);

    k_ln1<<<(NN * 32 + T - 1) / T, T>>>(x, gb, l1g, l1b);

    // MLP
    dim3 gm1(2, (NN + 127) / 128);
    k_sgemm<<<gm1, 256>>>(ph, W1, nullptr, pmid, NN, DD, 256, 1);
    dim3 gm2(1, (NN + 127) / 128);
    k_sgemm<<<gm2, 256>>>(pmid, W2, nullptr, pep, NN, 256, DD, 0);

    k_ln2<<<(NN * 32 + T - 1) / T, T>>>(l2g, l2b, out);
}

// round 3
// speedup vs baseline: 1.0398x; 1.0088x over previous
#include <cuda_runtime.h>
#include <math.h>

#define NN 50000
#define EE 640000
#define DD 128
#define EDIM 64
#define HH 4
#define ET (EE + NN)
#define LN_EPS 1e-5f

// ---------------------------------------------------------------------------
// Scratch (device globals: no allocation allowed)
// ---------------------------------------------------------------------------
__device__ __align__(16) float    g_xlr[(size_t)NN * 256];  // [xl | xr] fused projection
__device__ __align__(16) float    g_wlr[256 * DD];          // packed [Wl; Wr]
__device__ __align__(16) float    g_blr[256];               // packed [bl; br]
__device__ __align__(16) float    g_ep[(size_t)ET * DD];    // edge projection (reused for MLP2 out)
__device__ __align__(16) float    g_loop[NN * EDIM];
__device__              float     g_deg[NN];
__device__ __align__(16) unsigned g_amax[NN * HH];
__device__ __align__(16) float    g_denom[NN * HH];
__device__ __align__(16) float    g_logits[(size_t)ET * HH];
__device__ __align__(16) float    g_ex[(size_t)ET * HH];
__device__ __align__(16) float    g_accum[NN * DD];
__device__ __align__(16) float    g_h[NN * DD];
__device__ __align__(16) float    g_mid[(size_t)NN * 256];

// ---------------------------------------------------------------------------
// Helpers
// ---------------------------------------------------------------------------
__device__ __forceinline__ unsigned ford(float f) {
    unsigned u = __float_as_uint(f);
    return (u & 0x80000000u) ? ~u : (u | 0x80000000u);
}
__device__ __forceinline__ float iford(unsigned u) {
    return __uint_as_float((u & 0x80000000u) ? (u & 0x7FFFFFFFu) : ~u);
}
__device__ __forceinline__ void red_add_v4(float* p, float4 v) {
    asm volatile("red.global.add.v4.f32 [%0], {%1, %2, %3, %4};"
                 :: "l"(p), "f"(v.x), "f"(v.y), "f"(v.z), "f"(v.w) : "memory");
}
__device__ __forceinline__ float gelu_exact(float v) {
    return 0.5f * v * (1.0f + erff(v * 0.70710678118654752f));
}

// packed f32x2 ops (B300: fma.rn.f32x2 is full-rate; 3-reg FFMA is half-rate)
#define PACK2(d, lo, hi) asm("mov.b64 %0, {%1, %2};" : "=l"(d) : "f"(lo), "f"(hi))
#define BCAST2(d, v)     asm("mov.b64 %0, {%1, %1};" : "=l"(d) : "f"(v))
#define FMA2(acc, a, b)  asm("fma.rn.f32x2 %0, %1, %2, %0;" : "+l"(acc) : "l"(a), "l"(b))
#define UNPACK2(lo, hi, v) asm("mov.b64 {%0, %1}, %2;" : "=f"(lo), "=f"(hi) : "l"(v))

// ---------------------------------------------------------------------------
// Init
// ---------------------------------------------------------------------------
__global__ void k_init() {
    int i = blockIdx.x * blockDim.x + threadIdx.x;
    if (i < NN * DD)   g_accum[i] = 0.0f;
    if (i < NN * EDIM) g_loop[i] = 0.0f;
    if (i < NN)        g_deg[i] = 0.0f;
    if (i < NN * HH) { g_amax[i] = 0u; g_denom[i] = 0.0f; }
}

__global__ void k_pack(const float* __restrict__ Wl, const float* __restrict__ Wr,
                       const float* __restrict__ bl, const float* __restrict__ br) {
    int i = blockIdx.x * blockDim.x + threadIdx.x;
    if (i < 128 * DD) {
        g_wlr[i] = Wl[i];
        g_wlr[128 * DD + i] = Wr[i];
    }
    if (i < 128) { g_blr[i] = bl[i]; g_blr[128 + i] = br[i]; }
}

__global__ void k_degloop(const int* __restrict__ ei, const float* __restrict__ ea) {
    int t = blockIdx.x * blockDim.x + threadIdx.x;
    if (t >= EE * 16) return;
    int e = t >> 4, q = t & 15;
    int dst = ei[EE + e];
    float4 v = *(const float4*)(ea + (size_t)e * EDIM + q * 4);
    red_add_v4(&g_loop[dst * EDIM + q * 4], v);
    if (q == 0) atomicAdd(&g_deg[dst], 1.0f);
}

__global__ void k_div() {
    int i = blockIdx.x * blockDim.x + threadIdx.x;
    if (i >= NN * EDIM) return;
    g_loop[i] /= fmaxf(g_deg[i >> 6], 1.0f);
}

// ---------------------------------------------------------------------------
// SGEMM: C[M,Nc] = A[M,K] @ B[Nc,K]^T (+bias) (+gelu)
// 128x128 tile, BK=8, 256 threads, 8x8 microtile, double-buffered smem,
// inner product via packed fma.rn.f32x2 (2 FMA/lane/instr).
// Requires K % 8 == 0, Nc % 128 == 0. M guarded.
// ---------------------------------------------------------------------------
__global__ __launch_bounds__(256, 2) void k_sgemm(
    const float* __restrict__ A, const float* __restrict__ B,
    const float* __restrict__ bias, float* __restrict__ C,
    int M, int K, int Nc, int act)
{
    __shared__ __align__(16) float As[2][8][132];
    __shared__ __align__(16) float Bs[2][8][132];
    int tid = threadIdx.x;
    int m0 = blockIdx.y * 128, n0 = blockIdx.x * 128;
    int tx = tid & 15, ty = tid >> 4;      // 16x16 thread grid

    int lr = tid >> 1;                     // 0..127 (tile row for loads)
    int lk = (tid & 1) * 4;                // k 0 or 4

    const float* aptr = A + (size_t)(m0 + lr) * K + lk;
    const float* bptr = B + (size_t)(n0 + lr) * K + lk;
    bool aval = (m0 + lr) < M;

    float4 av = aval ? *(const float4*)aptr : make_float4(0.f,0.f,0.f,0.f);
    float4 bv = *(const float4*)bptr;

    // acc2[i][j]: packed pair for output cols (2j, 2j+1) within each 8-col half
    unsigned long long acc2[8][4];
#pragma unroll
    for (int i = 0; i < 8; i++)
#pragma unroll
        for (int j = 0; j < 4; j++) acc2[i][j] = 0ULL;

    int nk = K >> 3;
    int buf = 0;

    As[0][lk+0][lr] = av.x; As[0][lk+1][lr] = av.y;
    As[0][lk+2][lr] = av.z; As[0][lk+3][lr] = av.w;
    Bs[0][lk+0][lr] = bv.x; Bs[0][lk+1][lr] = bv.y;
    Bs[0][lk+2][lr] = bv.z; Bs[0][lk+3][lr] = bv.w;
    __syncthreads();

    for (int it = 0; it < nk; it++) {
        if (it + 1 < nk) {
            av = aval ? *(const float4*)(aptr + (it + 1) * 8) : make_float4(0.f,0.f,0.f,0.f);
            bv = *(const float4*)(bptr + (it + 1) * 8);
        }
#pragma unroll
        for (int k = 0; k < 8; k++) {
            float4 a0 = *(float4*)&As[buf][k][ty * 4];
            float4 a1 = *(float4*)&As[buf][k][64 + ty * 4];
            float4 b0 = *(float4*)&Bs[buf][k][tx * 4];
            float4 b1 = *(float4*)&Bs[buf][k][64 + tx * 4];
            unsigned long long bp[4];
            PACK2(bp[0], b0.x, b0.y); PACK2(bp[1], b0.z, b0.w);
            PACK2(bp[2], b1.x, b1.y); PACK2(bp[3], b1.z, b1.w);
            float a[8] = {a0.x, a0.y, a0.z, a0.w, a1.x, a1.y, a1.z, a1.w};
#pragma unroll
            for (int i = 0; i < 8; i++) {
                unsigned long long aa;
                BCAST2(aa, a[i]);
                FMA2(acc2[i][0], aa, bp[0]);
                FMA2(acc2[i][1], aa, bp[1]);
                FMA2(acc2[i][2], aa, bp[2]);
                FMA2(acc2[i][3], aa, bp[3]);
            }
        }
        if (it + 1 < nk) {
            int nb = buf ^ 1;
            As[nb][lk+0][lr] = av.x; As[nb][lk+1][lr] = av.y;
            As[nb][lk+2][lr] = av.z; As[nb][lk+3][lr] = av.w;
            Bs[nb][lk+0][lr] = bv.x; Bs[nb][lk+1][lr] = bv.y;
            Bs[nb][lk+2][lr] = bv.z; Bs[nb][lk+3][lr] = bv.w;
            __syncthreads();
            buf = nb;
        }
    }

    // Epilogue: rows {ty*4+i, 64+ty*4+i}, cols {tx*4.., 64+tx*4..}
#pragma unroll
    for (int ih = 0; ih < 2; ih++) {
#pragma unroll
        for (int i = 0; i < 4; i++) {
            int row = m0 + ih * 64 + ty * 4 + i;
            if (row >= M) continue;
            int ai = ih * 4 + i;
#pragma unroll
            for (int jh = 0; jh < 2; jh++) {
                int col = n0 + jh * 64 + tx * 4;
                float4 r;
                UNPACK2(r.x, r.y, acc2[ai][jh * 2 + 0]);
                UNPACK2(r.z, r.w, acc2[ai][jh * 2 + 1]);
                if (bias) {
                    float4 bb = *(const float4*)(bias + col);
                    r.x += bb.x; r.y += bb.y; r.z += bb.z; r.w += bb.w;
                }
                if (act == 1) {
                    r.x = gelu_exact(r.x); r.y = gelu_exact(r.y);
                    r.z = gelu_exact(r.z); r.w = gelu_exact(r.w);
                }
                *(float4*)(C + (size_t)row * Nc + col) = r;
            }
        }
    }
}

// ---------------------------------------------------------------------------
// Edge logits + segment max (warp per edge). xl = g_xlr[.,0:128], xr = [.,128:256]
// ---------------------------------------------------------------------------
__global__ void k_logits(const int* __restrict__ ei, const float* __restrict__ att) {
    int w = (blockIdx.x * blockDim.x + threadIdx.x) >> 5;
    if (w >= ET) return;
    int lane = threadIdx.x & 31;
    int src = (w < EE) ? ei[w] : (w - EE);
    int dst = (w < EE) ? ei[EE + w] : (w - EE);
    const float* ep = g_ep + (size_t)w * DD;
    const float* xl = g_xlr + (size_t)src * 256;
    const float* xr = g_xlr + (size_t)dst * 256 + 128;

    float p0, p1, p2, p3;
    {
        int i0 = lane, i1 = 32 + lane, i2 = 64 + lane, i3 = 96 + lane;
        float v0 = xl[i0] + xr[i0] + __ldcs(ep + i0);
        float v1 = xl[i1] + xr[i1] + __ldcs(ep + i1);
        float v2 = xl[i2] + xr[i2] + __ldcs(ep + i2);
        float v3 = xl[i3] + xr[i3] + __ldcs(ep + i3);
        v0 = (v0 > 0.f) ? v0 : 0.2f * v0;
        v1 = (v1 > 0.f) ? v1 : 0.2f * v1;
        v2 = (v2 > 0.f) ? v2 : 0.2f * v2;
        v3 = (v3 > 0.f) ? v3 : 0.2f * v3;
        p0 = v0 * att[i0]; p1 = v1 * att[i1];
        p2 = v2 * att[i2]; p3 = v3 * att[i3];
    }
#pragma unroll
    for (int off = 16; off; off >>= 1) {
        p0 += __shfl_xor_sync(0xFFFFFFFFu, p0, off);
        p1 += __shfl_xor_sync(0xFFFFFFFFu, p1, off);
        p2 += __shfl_xor_sync(0xFFFFFFFFu, p2, off);
        p3 += __shfl_xor_sync(0xFFFFFFFFu, p3, off);
    }
    if (lane < 4) {
        float lv = (lane == 0) ? p0 : (lane == 1) ? p1 : (lane == 2) ? p2 : p3;
        g_logits[(size_t)w * 4 + lane] = lv;
        atomicMax(&g_amax[dst * 4 + lane], ford(lv));
    }
}

__global__ void k_exps(const int* __restrict__ ei) {
    int t = blockIdx.x * blockDim.x + threadIdx.x;
    if (t >= ET) return;
    int dst = (t < EE) ? ei[EE + t] : (t - EE);
    float4 lg = *(float4*)&g_logits[(size_t)t * 4];
    uint4 am = *(uint4*)&g_amax[dst * 4];
    float4 e;
    e.x = expf(lg.x - iford(am.x));
    e.y = expf(lg.y - iford(am.y));
    e.z = expf(lg.z - iford(am.z));
    e.w = expf(lg.w - iford(am.w));
    *(float4*)&g_ex[(size_t)t * 4] = e;
    red_add_v4(&g_denom[dst * 4], e);
}

__global__ void k_agg(const int* __restrict__ ei, float* __restrict__ outAlpha) {
    int w = (blockIdx.x * blockDim.x + threadIdx.x) >> 5;
    if (w >= ET) return;
    int lane = threadIdx.x & 31;
    int src = (w < EE) ? ei[w] : (w - EE);
    int dst = (w < EE) ? ei[EE + w] : (w - EE);
    int h = lane >> 3;
    float a = g_ex[(size_t)w * 4 + h] / g_denom[dst * 4 + h];
    float4 x = *(const float4*)&g_xlr[(size_t)src * 256 + lane * 4];
    red_add_v4(&g_accum[dst * DD + lane * 4],
               make_float4(x.x * a, x.y * a, x.z * a, x.w * a));
    if (outAlpha != nullptr && lane < 4)
        outAlpha[(size_t)w * 4 + lane] =
            g_ex[(size_t)w * 4 + lane] / g_denom[dst * 4 + lane];
}

__global__ void k_ei(const int* __restrict__ ei, float* __restrict__ outEI) {
    int t = blockIdx.x * blockDim.x + threadIdx.x;
    if (t >= ET) return;
    int s = (t < EE) ? ei[t] : (t - EE);
    int d = (t < EE) ? ei[EE + t] : (t - EE);
    outEI[t] = (float)s;
    outEI[ET + t] = (float)d;
}

__global__ void k_ln1(const float* __restrict__ x, const float* __restrict__ gb,
                      const float* __restrict__ gam, const float* __restrict__ bet) {
    int w = (blockIdx.x * blockDim.x + threadIdx.x) >> 5;
    if (w >= NN) return;
    int lane = threadIdx.x & 31;
    float v[4];
#pragma unroll
    for (int r = 0; r < 4; r++) {
        int idx = r * 32 + lane;
        v[r] = x[(size_t)w * DD + idx] + g_accum[(size_t)w * DD + idx] + gb[idx];
    }
    float s = v[0] + v[1] + v[2] + v[3];
#pragma unroll
    for (int off = 16; off; off >>= 1) s += __shfl_xor_sync(0xFFFFFFFFu, s, off);
    float mu = s * (1.0f / 128.0f);
    float q = 0.f;
#pragma unroll
    for (int r = 0; r < 4; r++) { float d = v[r] - mu; q += d * d; }
#pragma unroll
    for (int off = 16; off; off >>= 1) q += __shfl_xor_sync(0xFFFFFFFFu, q, off);
    float rstd = rsqrtf(q * (1.0f / 128.0f) + LN_EPS);
#pragma unroll
    for (int r = 0; r < 4; r++) {
        int idx = r * 32 + lane;
        g_h[(size_t)w * DD + idx] = (v[r] - mu) * rstd * gam[idx] + bet[idx];
    }
}

// LN2: out = LayerNorm(h + mlp2) ; mlp2 result lives in g_ep (reused)
__global__ void k_ln2(const float* __restrict__ gam, const float* __restrict__ bet,
                      float* __restrict__ out) {
    int w = (blockIdx.x * blockDim.x + threadIdx.x) >> 5;
    if (w >= NN) return;
    int lane = threadIdx.x & 31;
    float v[4];
#pragma unroll
    for (int r = 0; r < 4; r++) {
        int idx = r * 32 + lane;
        v[r] = g_h[(size_t)w * DD + idx] + g_ep[(size_t)w * DD + idx];
    }
    float s = v[0] + v[1] + v[2] + v[3];
#pragma unroll
    for (int off = 16; off; off >>= 1) s += __shfl_xor_sync(0xFFFFFFFFu, s, off);
    float mu = s * (1.0f / 128.0f);
    float q = 0.f;
#pragma unroll
    for (int r = 0; r < 4; r++) { float d = v[r] - mu; q += d * d; }
#pragma unroll
    for (int off = 16; off; off >>= 1) q += __shfl_xor_sync(0xFFFFFFFFu, q, off);
    float rstd = rsqrtf(q * (1.0f / 128.0f) + LN_EPS);
#pragma unroll
    for (int r = 0; r < 4; r++) {
        int idx = r * 32 + lane;
        out[(size_t)w * DD + idx] = (v[r] - mu) * rstd * gam[idx] + bet[idx];
    }
}

// ---------------------------------------------------------------------------
// Launch
// ---------------------------------------------------------------------------
extern "C" void kernel_launch(void* const* d_in, const int* in_sizes, int n_in,
                              void* d_out, int out_size) {
    const float* x    = (const float*)d_in[0];
    const int*   ei   = (const int*)d_in[1];
    const float* ea   = (const float*)d_in[2];
    const float* Wl   = (const float*)d_in[3];
    const float* bl   = (const float*)d_in[4];
    const float* Wr   = (const float*)d_in[5];
    const float* br   = (const float*)d_in[6];
    const float* We   = (const float*)d_in[7];
    const float* att  = (const float*)d_in[8];
    const float* gb   = (const float*)d_in[9];
    const float* l1g  = (const float*)d_in[10];
    const float* l1b  = (const float*)d_in[11];
    const float* l2g  = (const float*)d_in[12];
    const float* l2b  = (const float*)d_in[13];
    const float* W1   = (const float*)d_in[14];
    const float* W2   = (const float*)d_in[15];
    float* out = (float*)d_out;

    long long full = (long long)NN * DD + 2LL * ET + (long long)ET * HH;
    bool fullout = ((long long)out_size == full);
    float* outEI    = fullout ? out + (size_t)NN * DD : nullptr;
    float* outAlpha = fullout ? out + (size_t)NN * DD + 2 * (size_t)ET : nullptr;

    float *pxlr, *pwlr, *pblr, *pep, *ploop, *ph, *pmid;
    cudaGetSymbolAddress((void**)&pxlr, g_xlr);
    cudaGetSymbolAddress((void**)&pwlr, g_wlr);
    cudaGetSymbolAddress((void**)&pblr, g_blr);
    cudaGetSymbolAddress((void**)&pep, g_ep);
    cudaGetSymbolAddress((void**)&ploop, g_loop);
    cudaGetSymbolAddress((void**)&ph, g_h);
    cudaGetSymbolAddress((void**)&pmid, g_mid);

    const int T = 256;
    k_init<<<(NN * DD + T - 1) / T, T>>>();
    k_pack<<<(128 * DD + T - 1) / T, T>>>(Wl, Wr, bl, br);
    k_degloop<<<(EE * 16 + T - 1) / T, T>>>(ei, ea);
    k_div<<<(NN * EDIM + T - 1) / T, T>>>();

    // fused xl|xr projection: [N,128] @ [256,128]^T -> [N,256]
    dim3 gxlr(2, (NN + 127) / 128);
    k_sgemm<<<gxlr, 256>>>(x, pwlr, pblr, pxlr, NN, DD, 256, 0);

    // edge projections
    dim3 ge1(1, (EE + 127) / 128);
    k_sgemm<<<ge1, 256>>>(ea, We, nullptr, pep, EE, EDIM, DD, 0);
    dim3 ge2(1, (NN + 127) / 128);
    k_sgemm<<<ge2, 256>>>(ploop, We, nullptr, pep + (size_t)EE * DD, NN, EDIM, DD, 0);

    k_logits<<<(ET * 32 + T - 1) / T, T>>>(ei, att);
    k_exps<<<(ET + T - 1) / T, T>>>(ei);
    k_agg<<<(ET * 32 + T - 1) / T, T>>>(ei, outAlpha);
    if (fullout) k_ei<<<(ET + T - 1) / T, T>>>(ei, outEI);

    k_ln1<<<(NN * 32 + T - 1) / T, T>>>(x, gb, l1g, l1b);

    // MLP
    dim3 gm1(2, (NN + 127) / 128);
    k_sgemm<<<gm1, 256>>>(ph, W1, nullptr, pmid, NN, DD, 256, 1);
    dim3 gm2(1, (NN + 127) / 128);
    k_sgemm<<<gm2, 256>>>(pmid, W2, nullptr, pep, NN, 256, DD, 0);

    k_ln2<<<(NN * 32 + T - 1) / T, T>>>(l2g, l2b, out);
}

// round 5
// speedup vs baseline: 1.0971x; 1.0552x over previous
#include <cuda_runtime.h>
#include <math.h>

#define NN 50000
#define EE 640000
#define DD 128
#define EDIM 64
#define HH 4
#define ET (EE + NN)
#define LN_EPS 1e-5f
#define NBLK ((NN + 255) / 256)

// ---------------------------------------------------------------------------
// Scratch (device globals)
// ---------------------------------------------------------------------------
__device__ __align__(16) float g_xlr[(size_t)NN * 256];   // [xl | xr]
__device__ __align__(16) float g_wlr[256 * DD];
__device__ __align__(16) float g_blr[256];
__device__ __align__(16) float g_ep[(size_t)ET * DD];     // edge projection (reused for MLP2 out)
__device__ __align__(16) float g_loop[NN * EDIM];
__device__ __align__(16) float g_logits[(size_t)ET * HH];
__device__ __align__(16) float g_amaxf[NN * HH];
__device__ __align__(16) float g_invdn[NN * HH];
__device__ __align__(16) float g_accum[NN * DD];
__device__ __align__(16) float g_h[NN * DD];
__device__ __align__(16) float g_mid[(size_t)NN * 256];
// CSR
__device__ int g_cnt[NN];
__device__ int g_cursor[NN];
__device__ int g_part[NN];
__device__ int g_blksum[NBLK];
__device__ int g_blkoff[NBLK];
__device__ int g_rowstart[NN];
__device__ int g_csr[EE];

// ---------------------------------------------------------------------------
// Helpers
// ---------------------------------------------------------------------------
__device__ __forceinline__ float gelu_exact(float v) {
    return 0.5f * v * (1.0f + erff(v * 0.70710678118654752f));
}
#define PACK2(d, lo, hi) asm("mov.b64 %0, {%1, %2};" : "=l"(d) : "f"(lo), "f"(hi))
#define BCAST2(d, v)     asm("mov.b64 %0, {%1, %1};" : "=l"(d) : "f"(v))
#define FMA2(acc, a, b)  asm("fma.rn.f32x2 %0, %1, %2, %0;" : "+l"(acc) : "l"(a), "l"(b))
#define UNPACK2(lo, hi, v) asm("mov.b64 {%0, %1}, %2;" : "=f"(lo), "=f"(hi) : "l"(v))

// ---------------------------------------------------------------------------
// CSR build
// ---------------------------------------------------------------------------
__global__ void k_init0() {
    int i = blockIdx.x * blockDim.x + threadIdx.x;
    if (i < NN) { g_cnt[i] = 0; g_cursor[i] = 0; }
}
__global__ void k_hist(const int* __restrict__ ei) {
    int t = blockIdx.x * blockDim.x + threadIdx.x;
    if (t >= EE) return;
    atomicAdd(&g_cnt[ei[EE + t]], 1);
}
__global__ void k_scan1() {
    __shared__ int s[256];
    int tid = threadIdx.x;
    int i = blockIdx.x * 256 + tid;
    int c = (i < NN) ? g_cnt[i] : 0;
    s[tid] = c;
    __syncthreads();
#pragma unroll
    for (int off = 1; off < 256; off <<= 1) {
        int v = (tid >= off) ? s[tid - off] : 0;
        __syncthreads();
        s[tid] += v;
        __syncthreads();
    }
    int incl = s[tid];
    if (i < NN) g_part[i] = incl - c;
    if (tid == 255) g_blksum[blockIdx.x] = incl;
}
__global__ void k_scan2() {
    __shared__ int s[256];
    int tid = threadIdx.x;
    int c = (tid < NBLK) ? g_blksum[tid] : 0;
    s[tid] = c;
    __syncthreads();
#pragma unroll
    for (int off = 1; off < 256; off <<= 1) {
        int v = (tid >= off) ? s[tid - off] : 0;
        __syncthreads();
        s[tid] += v;
        __syncthreads();
    }
    if (tid < NBLK) g_blkoff[tid] = s[tid] - c;
}
__global__ void k_scan3() {
    int i = blockIdx.x * blockDim.x + threadIdx.x;
    if (i < NN) g_rowstart[i] = g_part[i] + g_blkoff[i >> 8];
}
__global__ void k_fill(const int* __restrict__ ei) {
    int t = blockIdx.x * blockDim.x + threadIdx.x;
    if (t >= EE) return;
    int dst = ei[EE + t];
    int pos = g_rowstart[dst] + atomicAdd(&g_cursor[dst], 1);
    g_csr[pos] = t;
}

// loop_attr: mean of incoming edge_attr (warp per node)
__global__ void k_loopg(const float* __restrict__ ea) {
    int w = (blockIdx.x * blockDim.x + threadIdx.x) >> 5;
    if (w >= NN) return;
    int lane = threadIdx.x & 31;
    int start = g_rowstart[w], len = g_cnt[w];
    float2 acc = make_float2(0.f, 0.f);
    for (int i = 0; i < len; i++) {
        int e = g_csr[start + i];
        float2 v = *(const float2*)(ea + (size_t)e * EDIM + lane * 2);
        acc.x += v.x; acc.y += v.y;
    }
    float sc = 1.0f / fmaxf((float)len, 1.0f);
    *(float2*)&g_loop[(size_t)w * EDIM + lane * 2] = make_float2(acc.x * sc, acc.y * sc);
}

__global__ void k_pack(const float* __restrict__ Wl, const float* __restrict__ Wr,
                       const float* __restrict__ bl, const float* __restrict__ br) {
    int i = blockIdx.x * blockDim.x + threadIdx.x;
    if (i < 128 * DD) {
        g_wlr[i] = Wl[i];
        g_wlr[128 * DD + i] = Wr[i];
    }
    if (i < 128) { g_blr[i] = bl[i]; g_blr[128 + i] = br[i]; }
}

// ---------------------------------------------------------------------------
// SGEMM: C[M,Nc] = A[M,K] @ B[Nc,K]^T (+bias) (+gelu), f32x2 inner product
// ---------------------------------------------------------------------------
__global__ __launch_bounds__(256, 2) void k_sgemm(
    const float* __restrict__ A, const float* __restrict__ B,
    const float* __restrict__ bias, float* __restrict__ C,
    int M, int K, int Nc, int act)
{
    __shared__ __align__(16) float As[2][8][132];
    __shared__ __align__(16) float Bs[2][8][132];
    int tid = threadIdx.x;
    int m0 = blockIdx.y * 128, n0 = blockIdx.x * 128;
    int tx = tid & 15, ty = tid >> 4;
    int lr = tid >> 1;
    int lk = (tid & 1) * 4;

    const float* aptr = A + (size_t)(m0 + lr) * K + lk;
    const float* bptr = B + (size_t)(n0 + lr) * K + lk;
    bool aval = (m0 + lr) < M;

    float4 av = aval ? *(const float4*)aptr : make_float4(0.f,0.f,0.f,0.f);
    float4 bv = *(const float4*)bptr;

    unsigned long long acc2[8][4];
#pragma unroll
    for (int i = 0; i < 8; i++)
#pragma unroll
        for (int j = 0; j < 4; j++) acc2[i][j] = 0ULL;

    int nk = K >> 3;
    int buf = 0;

    As[0][lk+0][lr] = av.x; As[0][lk+1][lr] = av.y;
    As[0][lk+2][lr] = av.z; As[0][lk+3][lr] = av.w;
    Bs[0][lk+0][lr] = bv.x; Bs[0][lk+1][lr] = bv.y;
    Bs[0][lk+2][lr] = bv.z; Bs[0][lk+3][lr] = bv.w;
    __syncthreads();

    for (int it = 0; it < nk; it++) {
        if (it + 1 < nk) {
            av = aval ? *(const float4*)(aptr + (it + 1) * 8) : make_float4(0.f,0.f,0.f,0.f);
            bv = *(const float4*)(bptr + (it + 1) * 8);
        }
#pragma unroll
        for (int k = 0; k < 8; k++) {
            float4 a0 = *(float4*)&As[buf][k][ty * 4];
            float4 a1 = *(float4*)&As[buf][k][64 + ty * 4];
            float4 b0 = *(float4*)&Bs[buf][k][tx * 4];
            float4 b1 = *(float4*)&Bs[buf][k][64 + tx * 4];
            unsigned long long bp[4];
            PACK2(bp[0], b0.x, b0.y); PACK2(bp[1], b0.z, b0.w);
            PACK2(bp[2], b1.x, b1.y); PACK2(bp[3], b1.z, b1.w);
            float a[8] = {a0.x, a0.y, a0.z, a0.w, a1.x, a1.y, a1.z, a1.w};
#pragma unroll
            for (int i = 0; i < 8; i++) {
                unsigned long long aa;
                BCAST2(aa, a[i]);
                FMA2(acc2[i][0], aa, bp[0]);
                FMA2(acc2[i][1], aa, bp[1]);
                FMA2(acc2[i][2], aa, bp[2]);
                FMA2(acc2[i][3], aa, bp[3]);
            }
        }
        if (it + 1 < nk) {
            int nb = buf ^ 1;
            As[nb][lk+0][lr] = av.x; As[nb][lk+1][lr] = av.y;
            As[nb][lk+2][lr] = av.z; As[nb][lk+3][lr] = av.w;
            Bs[nb][lk+0][lr] = bv.x; Bs[nb][lk+1][lr] = bv.y;
            Bs[nb][lk+2][lr] = bv.z; Bs[nb][lk+3][lr] = bv.w;
            __syncthreads();
            buf = nb;
        }
    }

#pragma unroll
    for (int ih = 0; ih < 2; ih++) {
#pragma unroll
        for (int i = 0; i < 4; i++) {
            int row = m0 + ih * 64 + ty * 4 + i;
            if (row >= M) continue;
            int ai = ih * 4 + i;
#pragma unroll
            for (int jh = 0; jh < 2; jh++) {
                int col = n0 + jh * 64 + tx * 4;
                float4 r;
                UNPACK2(r.x, r.y, acc2[ai][jh * 2 + 0]);
                UNPACK2(r.z, r.w, acc2[ai][jh * 2 + 1]);
                if (bias) {
                    float4 bb = *(const float4*)(bias + col);
                    r.x += bb.x; r.y += bb.y; r.z += bb.z; r.w += bb.w;
                }
                if (act == 1) {
                    r.x = gelu_exact(r.x); r.y = gelu_exact(r.y);
                    r.z = gelu_exact(r.z); r.w = gelu_exact(r.w);
                }
                *(float4*)(C + (size_t)row * Nc + col) = r;
            }
        }
    }
}

// ---------------------------------------------------------------------------
// Edge logits (warp per edge) — no atomics, just store
// ---------------------------------------------------------------------------
__global__ void k_logits(const int* __restrict__ ei, const float* __restrict__ att) {
    int w = (blockIdx.x * blockDim.x + threadIdx.x) >> 5;
    if (w >= ET) return;
    int lane = threadIdx.x & 31;
    int src = (w < EE) ? ei[w] : (w - EE);
    int dst = (w < EE) ? ei[EE + w] : (w - EE);
    const float* ep = g_ep + (size_t)w * DD;
    const float* xl = g_xlr + (size_t)src * 256;
    const float* xr = g_xlr + (size_t)dst * 256 + 128;

    float p0, p1, p2, p3;
    {
        int i0 = lane, i1 = 32 + lane, i2 = 64 + lane, i3 = 96 + lane;
        float v0 = xl[i0] + xr[i0] + __ldcs(ep + i0);
        float v1 = xl[i1] + xr[i1] + __ldcs(ep + i1);
        float v2 = xl[i2] + xr[i2] + __ldcs(ep + i2);
        float v3 = xl[i3] + xr[i3] + __ldcs(ep + i3);
        v0 = (v0 > 0.f) ? v0 : 0.2f * v0;
        v1 = (v1 > 0.f) ? v1 : 0.2f * v1;
        v2 = (v2 > 0.f) ? v2 : 0.2f * v2;
        v3 = (v3 > 0.f) ? v3 : 0.2f * v3;
        p0 = v0 * att[i0]; p1 = v1 * att[i1];
        p2 = v2 * att[i2]; p3 = v3 * att[i3];
    }
#pragma unroll
    for (int off = 16; off; off >>= 1) {
        p0 += __shfl_xor_sync(0xFFFFFFFFu, p0, off);
        p1 += __shfl_xor_sync(0xFFFFFFFFu, p1, off);
        p2 += __shfl_xor_sync(0xFFFFFFFFu, p2, off);
        p3 += __shfl_xor_sync(0xFFFFFFFFu, p3, off);
    }
    if (lane < 4) {
        float lv = (lane == 0) ? p0 : (lane == 1) ? p1 : (lane == 2) ? p2 : p3;
        g_logits[(size_t)w * 4 + lane] = lv;
    }
}

// ---------------------------------------------------------------------------
// Segment softmax + aggregation, warp per node. No atomics, no per-lane div.
// ---------------------------------------------------------------------------
__global__ void k_softagg(const int* __restrict__ ei) {
    int w = (blockIdx.x * blockDim.x + threadIdx.x) >> 5;
    if (w >= NN) return;
    int lane = threadIdx.x & 31;
    int start = g_rowstart[w], len = g_cnt[w];

    // pass 1: max over incoming edges (lane-strided)
    float4 am = make_float4(-3.0e38f, -3.0e38f, -3.0e38f, -3.0e38f);
    for (int i = lane; i < len; i += 32) {
        int e = g_csr[start + i];
        float4 lg = *(const float4*)&g_logits[(size_t)e * 4];
        am.x = fmaxf(am.x, lg.x); am.y = fmaxf(am.y, lg.y);
        am.z = fmaxf(am.z, lg.z); am.w = fmaxf(am.w, lg.w);
    }
#pragma unroll
    for (int off = 16; off; off >>= 1) {
        am.x = fmaxf(am.x, __shfl_xor_sync(0xFFFFFFFFu, am.x, off));
        am.y = fmaxf(am.y, __shfl_xor_sync(0xFFFFFFFFu, am.y, off));
        am.z = fmaxf(am.z, __shfl_xor_sync(0xFFFFFFFFu, am.z, off));
        am.w = fmaxf(am.w, __shfl_xor_sync(0xFFFFFFFFu, am.w, off));
    }
    float4 ls = *(const float4*)&g_logits[((size_t)EE + w) * 4];  // self-loop
    am.x = fmaxf(am.x, ls.x); am.y = fmaxf(am.y, ls.y);
    am.z = fmaxf(am.z, ls.z); am.w = fmaxf(am.w, ls.w);

    // pass 2: denom
    float4 dn = make_float4(0.f, 0.f, 0.f, 0.f);
    for (int i = lane; i < len; i += 32) {
        int e = g_csr[start + i];
        float4 lg = *(const float4*)&g_logits[(size_t)e * 4];
        dn.x += expf(lg.x - am.x); dn.y += expf(lg.y - am.y);
        dn.z += expf(lg.z - am.z); dn.w += expf(lg.w - am.w);
    }
#pragma unroll
    for (int off = 16; off; off >>= 1) {
        dn.x += __shfl_xor_sync(0xFFFFFFFFu, dn.x, off);
        dn.y += __shfl_xor_sync(0xFFFFFFFFu, dn.y, off);
        dn.z += __shfl_xor_sync(0xFFFFFFFFu, dn.z, off);
        dn.w += __shfl_xor_sync(0xFFFFFFFFu, dn.w, off);
    }
    dn.x += expf(ls.x - am.x); dn.y += expf(ls.y - am.y);
    dn.z += expf(ls.z - am.z); dn.w += expf(ls.w - am.w);

    float4 inv = make_float4(1.0f / dn.x, 1.0f / dn.y, 1.0f / dn.z, 1.0f / dn.w);
    if (lane == 0) {
        *(float4*)&g_amaxf[w * 4] = am;
        *(float4*)&g_invdn[w * 4] = inv;
    }

    // pass 3: aggregation. lane handles cols lane*4..lane*4+3 (head = lane>>3).
    int h = lane >> 3;
    int l3 = lane & 3;
    float amc  = (l3 == 0) ? am.x  : (l3 == 1) ? am.y  : (l3 == 2) ? am.z  : am.w;
    float invc = (l3 == 0) ? inv.x : (l3 == 1) ? inv.y : (l3 == 2) ? inv.z : inv.w;

    float lsc = (l3 == 0) ? ls.x : (l3 == 1) ? ls.y : (l3 == 2) ? ls.z : ls.w;
    float ahs = expf(lsc - amc) * invc;               // valid on lanes 0-3
    float aself = __shfl_sync(0xFFFFFFFFu, ahs, h);

    const float4 xs = *(const float4*)&g_xlr[(size_t)w * 256 + lane * 4];
    float4 acc = make_float4(aself * xs.x, aself * xs.y, aself * xs.z, aself * xs.w);

    for (int i = 0; i < len; i++) {
        int e = g_csr[start + i];
        int s = ei[e];
        float lgc = g_logits[(size_t)e * 4 + l3];      // same 16B sector, broadcast
        float aeh = expf(lgc - amc) * invc;            // valid on lanes 0-3
        float a = __shfl_sync(0xFFFFFFFFu, aeh, h);
        float4 xv = *(const float4*)&g_xlr[(size_t)s * 256 + lane * 4];
        acc.x += a * xv.x; acc.y += a * xv.y;
        acc.z += a * xv.z; acc.w += a * xv.w;
    }
    *(float4*)&g_accum[(size_t)w * DD + lane * 4] = acc;
}

// alpha output (thread per edge incl self-loops)
__global__ void k_alpha(const int* __restrict__ ei, float* __restrict__ outAlpha) {
    int t = blockIdx.x * blockDim.x + threadIdx.x;
    if (t >= ET) return;
    int dst = (t < EE) ? ei[EE + t] : (t - EE);
    float4 lg = *(const float4*)&g_logits[(size_t)t * 4];
    float4 am = *(const float4*)&g_amaxf[dst * 4];
    float4 inv = *(const float4*)&g_invdn[dst * 4];
    float4 a;
    a.x = expf(lg.x - am.x) * inv.x;
    a.y = expf(lg.y - am.y) * inv.y;
    a.z = expf(lg.z - am.z) * inv.z;
    a.w = expf(lg.w - am.w) * inv.w;
    *(float4*)&outAlpha[(size_t)t * 4] = a;
}

__global__ void k_ei(const int* __restrict__ ei, float* __restrict__ outEI) {
    int t = blockIdx.x * blockDim.x + threadIdx.x;
    if (t >= ET) return;
    int s = (t < EE) ? ei[t] : (t - EE);
    int d = (t < EE) ? ei[EE + t] : (t - EE);
    outEI[t] = (float)s;
    outEI[ET + t] = (float)d;
}

__global__ void k_ln1(const float* __restrict__ x, const float* __restrict__ gb,
                      const float* __restrict__ gam, const float* __restrict__ bet) {
    int w = (blockIdx.x * blockDim.x + threadIdx.x) >> 5;
    if (w >= NN) return;
    int lane = threadIdx.x & 31;
    float v[4];
#pragma unroll
    for (int r = 0; r < 4; r++) {
        int idx = r * 32 + lane;
        v[r] = x[(size_t)w * DD + idx] + g_accum[(size_t)w * DD + idx] + gb[idx];
    }
    float s = v[0] + v[1] + v[2] + v[3];
#pragma unroll
    for (int off = 16; off; off >>= 1) s += __shfl_xor_sync(0xFFFFFFFFu, s, off);
    float mu = s * (1.0f / 128.0f);
    float q = 0.f;
#pragma unroll
    for (int r = 0; r < 4; r++) { float d = v[r] - mu; q += d * d; }
#pragma unroll
    for (int off = 16; off; off >>= 1) q += __shfl_xor_sync(0xFFFFFFFFu, q, off);
    float rstd = rsqrtf(q * (1.0f / 128.0f) + LN_EPS);
#pragma unroll
    for (int r = 0; r < 4; r++) {
        int idx = r * 32 + lane;
        g_h[(size_t)w * DD + idx] = (v[r] - mu) * rstd * gam[idx] + bet[idx];
    }
}

__global__ void k_ln2(const float* __restrict__ gam, const float* __restrict__ bet,
                      float* __restrict__ out) {
    int w = (blockIdx.x * blockDim.x + threadIdx.x) >> 5;
    if (w >= NN) return;
    int lane = threadIdx.x & 31;
    float v[4];
#pragma unroll
    for (int r = 0; r < 4; r++) {
        int idx = r * 32 + lane;
        v[r] = g_h[(size_t)w * DD + idx] + g_ep[(size_t)w * DD + idx];
    }
    float s = v[0] + v[1] + v[2] + v[3];
#pragma unroll
    for (int off = 16; off; off >>= 1) s += __shfl_xor_sync(0xFFFFFFFFu, s, off);
    float mu = s * (1.0f / 128.0f);
    float q = 0.f;
#pragma unroll
    for (int r = 0; r < 4; r++) { float d = v[r] - mu; q += d * d; }
#pragma unroll
    for (int off = 16; off; off >>= 1) q += __shfl_xor_sync(0xFFFFFFFFu, q, off);
    float rstd = rsqrtf(q * (1.0f / 128.0f) + LN_EPS);
#pragma unroll
    for (int r = 0; r < 4; r++) {
        int idx = r * 32 + lane;
        out[(size_t)w * DD + idx] = (v[r] - mu) * rstd * gam[idx] + bet[idx];
    }
}

// ---------------------------------------------------------------------------
// Launch
// ---------------------------------------------------------------------------
extern "C" void kernel_launch(void* const* d_in, const int* in_sizes, int n_in,
                              void* d_out, int out_size) {
    const float* x    = (const float*)d_in[0];
    const int*   ei   = (const int*)d_in[1];
    const float* ea   = (const float*)d_in[2];
    const float* Wl   = (const float*)d_in[3];
    const float* bl   = (const float*)d_in[4];
    const float* Wr   = (const float*)d_in[5];
    const float* br   = (const float*)d_in[6];
    const float* We   = (const float*)d_in[7];
    const float* att  = (const float*)d_in[8];
    const float* gb   = (const float*)d_in[9];
    const float* l1g  = (const float*)d_in[10];
    const float* l1b  = (const float*)d_in[11];
    const float* l2g  = (const float*)d_in[12];
    const float* l2b  = (const float*)d_in[13];
    const float* W1   = (const float*)d_in[14];
    const float* W2   = (const float*)d_in[15];
    float* out = (float*)d_out;

    long long full = (long long)NN * DD + 2LL * ET + (long long)ET * HH;
    bool fullout = ((long long)out_size == full);
    float* outEI    = fullout ? out + (size_t)NN * DD : nullptr;
    float* outAlpha = fullout ? out + (size_t)NN * DD + 2 * (size_t)ET : nullptr;

    float *pxlr, *pwlr, *pblr, *pep, *ploop, *ph, *pmid;
    cudaGetSymbolAddress((void**)&pxlr, g_xlr);
    cudaGetSymbolAddress((void**)&pwlr, g_wlr);
    cudaGetSymbolAddress((void**)&pblr, g_blr);
    cudaGetSymbolAddress((void**)&pep, g_ep);
    cudaGetSymbolAddress((void**)&ploop, g_loop);
    cudaGetSymbolAddress((void**)&ph, g_h);
    cudaGetSymbolAddress((void**)&pmid, g_mid);

    const int T = 256;
    // CSR build
    k_init0<<<(NN + T - 1) / T, T>>>();
    k_hist<<<(EE + T - 1) / T, T>>>(ei);
    k_scan1<<<NBLK, 256>>>();
    k_scan2<<<1, 256>>>();
    k_scan3<<<(NN + T - 1) / T, T>>>();
    k_fill<<<(EE + T - 1) / T, T>>>(ei);
    k_loopg<<<(NN * 32 + T - 1) / T, T>>>(ea);

    k_pack<<<(128 * DD + T - 1) / T, T>>>(Wl, Wr, bl, br);

    // fused xl|xr projection
    dim3 gxlr(2, (NN + 127) / 128);
    k_sgemm<<<gxlr, 256>>>(x, pwlr, pblr, pxlr, NN, DD, 256, 0);

    // edge projections
    dim3 ge1(1, (EE + 127) / 128);
    k_sgemm<<<ge1, 256>>>(ea, We, nullptr, pep, EE, EDIM, DD, 0);
    dim3 ge2(1, (NN + 127) / 128);
    k_sgemm<<<ge2, 256>>>(ploop, We, nullptr, pep + (size_t)EE * DD, NN, EDIM, DD, 0);

    k_logits<<<(ET * 32 + T - 1) / T, T>>>(ei, att);
    k_softagg<<<(NN * 32 + T - 1) / T, T>>>(ei);
    if (fullout) {
        k_alpha<<<(ET + T - 1) / T, T>>>(ei, outAlpha);
        k_ei<<<(ET + T - 1) / T, T>>>(ei, outEI);
    }

    k_ln1<<<(NN * 32 + T - 1) / T, T>>>(x, gb, l1g, l1b);

    dim3 gm1(2, (NN + 127) / 128);
    k_sgemm<<<gm1, 256>>>(ph, W1, nullptr, pmid, NN, DD, 256, 1);
    dim3 gm2(1, (NN + 127) / 128);
    k_sgemm<<<gm2, 256>>>(pmid, W2, nullptr, pep, NN, 256, DD, 0);

    k_ln2<<<(NN * 32 + T - 1) / T, T>>>(l2g, l2b, out);
}